// round 1
// baseline (speedup 1.0000x reference)
#include <cuda_runtime.h>
#include <math.h>

// Problem dims
#define L_SEQ 2048
#define BSZ   4
#define DM    1024
#define DI    2048
#define DS    16
#define DR    64
#define M_ROWS 8192   // BSZ * L_SEQ

// ---------------------------------------------------------------------------
// Scratch (static device arrays — no allocation at runtime)
// ---------------------------------------------------------------------------
// g_xz layout: [m][dir*4096 + c], c in [0,2048)=xi, [2048,4096)=z
__device__ float g_xz  [(size_t)M_ROWS * 8192];          // 268 MB
__device__ float g_xc  [2 * (size_t)M_ROWS * DI];        // 134 MB
__device__ float g_proj[2 * (size_t)M_ROWS * 96];        // 6.3 MB (dt_raw|B|C)
__device__ float g_dt  [2 * (size_t)M_ROWS * DI];        // 134 MB (pre-softplus)
__device__ float g_y   [2 * (size_t)M_ROWS * DI];        // 134 MB (gated y)

// ---------------------------------------------------------------------------
// Generic fp32 SIMT GEMM: C[M,N] = A[M,K] @ W[N,K]^T (+ C if beta)
// 128x128 tile, 256 threads, 8x8 per thread, K-step 8, float4 global loads.
// ---------------------------------------------------------------------------
__device__ __forceinline__ void gemm_body(
    const float* __restrict__ A, int lda,
    const float* __restrict__ W, int ldw,
    float* __restrict__ C, int ldc,
    int M, int N, int K, int beta)
{
    __shared__ float As[8][132];
    __shared__ float Ws[8][132];

    const int tid  = threadIdx.x;
    const int bm   = blockIdx.y * 128;
    const int bn   = blockIdx.x * 128;
    const int lrow = tid >> 1;            // 0..127
    const int lcol = (tid & 1) << 2;      // 0 or 4
    const int tx   = tid & 15;
    const int ty   = tid >> 4;

    float acc[8][8];
#pragma unroll
    for (int i = 0; i < 8; i++)
#pragma unroll
        for (int j = 0; j < 8; j++) acc[i][j] = 0.f;

    const int am = bm + lrow;
    const int wn = bn + lrow;
    const bool aok = am < M;
    const bool wok = wn < N;
    const float* Ap = A + (size_t)am * lda;
    const float* Wp = W + (size_t)wn * ldw;

    for (int k0 = 0; k0 < K; k0 += 8) {
        float4 av = aok ? *(const float4*)(Ap + k0 + lcol) : make_float4(0.f,0.f,0.f,0.f);
        float4 wv = wok ? *(const float4*)(Wp + k0 + lcol) : make_float4(0.f,0.f,0.f,0.f);
        __syncthreads();
        As[lcol+0][lrow] = av.x; As[lcol+1][lrow] = av.y;
        As[lcol+2][lrow] = av.z; As[lcol+3][lrow] = av.w;
        Ws[lcol+0][lrow] = wv.x; Ws[lcol+1][lrow] = wv.y;
        Ws[lcol+2][lrow] = wv.z; Ws[lcol+3][lrow] = wv.w;
        __syncthreads();
#pragma unroll
        for (int kk = 0; kk < 8; kk++) {
            float4 a0 = *(const float4*)&As[kk][ty * 8];
            float4 a1 = *(const float4*)&As[kk][ty * 8 + 4];
            float4 b0 = *(const float4*)&Ws[kk][tx * 8];
            float4 b1 = *(const float4*)&Ws[kk][tx * 8 + 4];
            float ar[8] = {a0.x,a0.y,a0.z,a0.w,a1.x,a1.y,a1.z,a1.w};
            float br[8] = {b0.x,b0.y,b0.z,b0.w,b1.x,b1.y,b1.z,b1.w};
#pragma unroll
            for (int i = 0; i < 8; i++)
#pragma unroll
                for (int j = 0; j < 8; j++)
                    acc[i][j] = fmaf(ar[i], br[j], acc[i][j]);
        }
    }

#pragma unroll
    for (int i = 0; i < 8; i++) {
        int m = bm + ty * 8 + i;
        if (m >= M) continue;
#pragma unroll
        for (int j = 0; j < 8; j++) {
            int n = bn + tx * 8 + j;
            if (n < N) {
                size_t idx = (size_t)m * ldc + n;
                C[idx] = beta ? (C[idx] + acc[i][j]) : acc[i][j];
            }
        }
    }
}

// ---- GEMM wrappers (bind device scratch arrays in device code) ------------

// xz = x @ in_proj_w^T  (both dirs fused: N = 2*4096 = 8192, weight contiguous)
__global__ void __launch_bounds__(256, 2) k_in_proj(const float* __restrict__ x,
                                                    const float* __restrict__ w) {
    gemm_body(x, DM, w, DM, g_xz, 8192, M_ROWS, 8192, DM, 0);
}

// proj[dir] = xc[dir] @ x_proj_w[dir]^T  (N=96)
__global__ void __launch_bounds__(256, 2) k_x_proj(const float* __restrict__ w) {
    int dir = blockIdx.z;
    gemm_body(g_xc + (size_t)dir * M_ROWS * DI, DI,
              w + (size_t)dir * 96 * DI, DI,
              g_proj + (size_t)dir * M_ROWS * 96, 96,
              M_ROWS, 96, DI, 0);
}

// dt_raw[dir] (cols 0..63 of proj, lda=96) @ dt_proj_w[dir]^T  (N=2048, K=64)
__global__ void __launch_bounds__(256, 2) k_dt_proj(const float* __restrict__ w) {
    int dir = blockIdx.z;
    gemm_body(g_proj + (size_t)dir * M_ROWS * 96, 96,
              w + (size_t)dir * DI * DR, DR,
              g_dt + (size_t)dir * M_ROWS * DI, DI,
              M_ROWS, DI, DR, 0);
}

// out (+)= y[dir] @ out_proj_w[dir]^T
__global__ void __launch_bounds__(256, 2) k_out_proj(const float* __restrict__ w,
                                                     float* __restrict__ out, int dir) {
    gemm_body(g_y + (size_t)dir * M_ROWS * DI, DI,
              w + (size_t)dir * DM * DI, DI,
              out, DM,
              M_ROWS, DM, DI, dir /* beta */);
}

// ---------------------------------------------------------------------------
// Depthwise causal conv (dir 0) / anti-causal conv (dir 1) + SiLU.
// dir 1 equivalence to flip->conv->flip: xc1[l] = cb + sum_k cw[k]*xi1[l+3-k]
// ---------------------------------------------------------------------------
__global__ void k_conv(const float* __restrict__ cw, const float* __restrict__ cb) {
    size_t idx = (size_t)blockIdx.x * blockDim.x + threadIdx.x;
    if (idx >= (size_t)2 * M_ROWS * DI) return;
    int e   = (int)(idx % DI);
    size_t r = idx / DI;
    int m   = (int)(r % M_ROWS);
    int dir = (int)(r / M_ROWS);
    int l = m % L_SEQ;
    int b = m / L_SEQ;

    float acc = cb[dir * DI + e];
    const float* w4 = cw + ((size_t)dir * DI + e) * 4;
#pragma unroll
    for (int k = 0; k < 4; k++) {
        int tl = (dir == 0) ? (l - 3 + k) : (l + 3 - k);
        if (tl >= 0 && tl < L_SEQ)
            acc = fmaf(w4[k], g_xz[((size_t)(b * L_SEQ + tl)) * 8192 + dir * 4096 + e], acc);
    }
    float xc = acc / (1.f + __expf(-acc));   // silu
    g_xc[((size_t)dir * M_ROWS + m) * DI + e] = xc;
}

// ---------------------------------------------------------------------------
// Selective scan. One thread per (dir, b, channel e); 16 states in registers.
// Fuses: softplus(dt), recurrence, y-reduction, +xc*D skip, *silu(z) gating.
// Block = 32 threads (one warp = 32 channels); B_t/C_t broadcast via smem.
// ---------------------------------------------------------------------------
__global__ void k_scan(const float* __restrict__ dt_b,
                       const float* __restrict__ A_log,
                       const float* __restrict__ Dp) {
    const int lane = threadIdx.x;           // 0..31
    const int dir  = blockIdx.z;
    const int b    = blockIdx.y;
    const int e    = blockIdx.x * 32 + lane;

    __shared__ float sB[16], sC[16];

    float a[16];
#pragma unroll
    for (int s = 0; s < 16; s++)
        a[s] = -__expf(A_log[((size_t)dir * DI + e) * 16 + s]);

    const float bias  = dt_b[dir * DI + e];
    const float dcoef = Dp[dir * DI + e];

    float h[16];
#pragma unroll
    for (int s = 0; s < 16; s++) h[s] = 0.f;

    const size_t base_de = (size_t)dir * M_ROWS * DI;
    const size_t proj_base = (size_t)dir * M_ROWS * 96;

    for (int t = 0; t < L_SEQ; t++) {
        const int tt = dir ? (L_SEQ - 1 - t) : t;
        const size_t m = (size_t)b * L_SEQ + tt;

        // lanes 0..15 -> B (cols 64..79), lanes 16..31 -> C (cols 80..95)
        float bc = g_proj[(proj_base + m * 96) + 64 + lane];
        if (lane < 16) sB[lane] = bc; else sC[lane - 16] = bc;
        __syncwarp();

        float v  = g_dt[base_de + m * DI + e] + bias;
        float dt = (v > 15.f) ? v : log1pf(__expf(v));     // softplus
        float x  = g_xc[base_de + m * DI + e];
        float z  = g_xz[m * 8192 + dir * 4096 + 2048 + e];
        float dtx = dt * x;

        float y = 0.f;
#pragma unroll
        for (int s = 0; s < 16; s++) {
            float dA = __expf(dt * a[s]);
            h[s] = fmaf(h[s], dA, dtx * sB[s]);
            y    = fmaf(h[s], sC[s], y);
        }
        float yv = fmaf(x, dcoef, y);
        float sz = z / (1.f + __expf(-z));                  // silu(z)
        g_y[base_de + m * DI + e] = yv * sz;
        __syncwarp();
    }
}

// ---------------------------------------------------------------------------
extern "C" void kernel_launch(void* const* d_in, const int* in_sizes, int n_in,
                              void* d_out, int out_size) {
    const float* x      = (const float*)d_in[0];
    const float* in_w   = (const float*)d_in[1];
    const float* conv_w = (const float*)d_in[2];
    const float* conv_b = (const float*)d_in[3];
    const float* x_w    = (const float*)d_in[4];
    const float* dt_w   = (const float*)d_in[5];
    const float* dt_bv  = (const float*)d_in[6];
    const float* A_log  = (const float*)d_in[7];
    const float* Dp     = (const float*)d_in[8];
    const float* out_w  = (const float*)d_in[9];
    float* out = (float*)d_out;

    // 1) xz = x @ [in_w_fwd ; in_w_bwd]^T   (M=8192, N=8192, K=1024)
    k_in_proj<<<dim3(64, 64), 256>>>(x, in_w);
    // 2) depthwise conv + silu -> xc
    k_conv<<<(2u * M_ROWS * DI) / 256, 256>>>(conv_w, conv_b);
    // 3) proj = xc @ x_proj_w^T  (per dir, N=96)
    k_x_proj<<<dim3(1, 64, 2), 256>>>(x_w);
    // 4) dt_raw @ dt_proj_w^T    (per dir, N=2048, K=64)
    k_dt_proj<<<dim3(16, 64, 2), 256>>>(dt_w);
    // 5) selective scan + gating -> g_y
    k_scan<<<dim3(DI / 32, BSZ, 2), 32>>>(dt_bv, A_log, Dp);
    // 6) out = y0 @ ow0^T ; out += y1 @ ow1^T
    k_out_proj<<<dim3(8, 64), 256>>>(out_w, out, 0);
    k_out_proj<<<dim3(8, 64), 256>>>(out_w, out, 1);
}

// round 3
// speedup vs baseline: 2.3576x; 2.3576x over previous
#include <cuda_runtime.h>
#include <cuda_bf16.h>
#include <cstdint>
#include <math.h>

// Problem dims
#define L_SEQ 2048
#define BSZ   4
#define DM    1024
#define DI    2048
#define DS    16
#define DR    64
#define M_ROWS 8192   // BSZ * L_SEQ

// ============================================================================
// Scratch (static device arrays)
// ============================================================================
__device__ float g_xz  [(size_t)M_ROWS * 8192];             // in_proj output (xi|z per dir)
__device__ float g_proj[2 * (size_t)M_ROWS * 96];           // x_proj output (dt_raw|B|C)
__device__ float g_dt  [2 * (size_t)M_ROWS * DI];           // dt_proj output (pre-softplus)

// bf16 hi/lo operand planes
__device__ __nv_bfloat16 g_x_hi  [(size_t)M_ROWS * DM],  g_x_lo  [(size_t)M_ROWS * DM];
__device__ __nv_bfloat16 g_inw_hi[(size_t)8192 * DM],    g_inw_lo[(size_t)8192 * DM];
__device__ __nv_bfloat16 g_xw_hi [2 * 96 * (size_t)DI],  g_xw_lo [2 * 96 * (size_t)DI];
__device__ __nv_bfloat16 g_dtw_hi[2 * (size_t)DI * DR],  g_dtw_lo[2 * (size_t)DI * DR];
__device__ __nv_bfloat16 g_ow_hi [2 * (size_t)DM * DI],  g_ow_lo [2 * (size_t)DM * DI];
__device__ __nv_bfloat16 g_xc_hi [2 * (size_t)M_ROWS * DI], g_xc_lo[2 * (size_t)M_ROWS * DI];
__device__ __nv_bfloat16 g_dtr_hi[2 * (size_t)M_ROWS * DR], g_dtr_lo[2 * (size_t)M_ROWS * DR];
__device__ __nv_bfloat16 g_y_hi  [2 * (size_t)M_ROWS * DI], g_y_lo [2 * (size_t)M_ROWS * DI];

__device__ __forceinline__ void split2(float v, __nv_bfloat16& h, __nv_bfloat16& l) {
    h = __float2bfloat16_rn(v);
    l = __float2bfloat16_rn(v - __bfloat162float(h));
}

// ============================================================================
// PTX helpers (all sm_80-class: valid on base sm_103 target)
// ============================================================================
__device__ __forceinline__ uint32_t smem_u32(const void* p) {
    uint32_t a;
    asm("{ .reg .u64 t; cvta.to.shared.u64 t, %1; cvt.u32.u64 %0, t; }" : "=r"(a) : "l"(p));
    return a;
}
__device__ __forceinline__ void cpa16(uint32_t dst, const void* src) {
    asm volatile("cp.async.cg.shared.global [%0], [%1], 16;" :: "r"(dst), "l"(src) : "memory");
}
__device__ __forceinline__ void cpa16p(uint32_t dst, const void* src, int sz) {
    asm volatile("cp.async.cg.shared.global [%0], [%1], 16, %2;" :: "r"(dst), "l"(src), "r"(sz) : "memory");
}
__device__ __forceinline__ void cp_commit() {
    asm volatile("cp.async.commit_group;" ::: "memory");
}
template <int N>
__device__ __forceinline__ void cp_wait() {
    asm volatile("cp.async.wait_group %0;" :: "n"(N) : "memory");
}
__device__ __forceinline__ void ldsm_x4(uint32_t* r, uint32_t addr) {
    asm volatile("ldmatrix.sync.aligned.m8n8.x4.shared.b16 {%0,%1,%2,%3}, [%4];"
                 : "=r"(r[0]), "=r"(r[1]), "=r"(r[2]), "=r"(r[3]) : "r"(addr));
}
__device__ __forceinline__ void ldsm_x2(uint32_t* r, uint32_t addr) {
    asm volatile("ldmatrix.sync.aligned.m8n8.x2.shared.b16 {%0,%1}, [%2];"
                 : "=r"(r[0]), "=r"(r[1]) : "r"(addr));
}
__device__ __forceinline__ void mma_bf16(float* d, const uint32_t* a, const uint32_t* b) {
    asm volatile("mma.sync.aligned.m16n8k16.row.col.f32.bf16.bf16.f32 "
                 "{%0,%1,%2,%3}, {%4,%5,%6,%7}, {%8,%9}, {%0,%1,%2,%3};"
                 : "+f"(d[0]), "+f"(d[1]), "+f"(d[2]), "+f"(d[3])
                 : "r"(a[0]), "r"(a[1]), "r"(a[2]), "r"(a[3]), "r"(b[0]), "r"(b[1]));
}

// ============================================================================
// HMMA GEMM: C[M,N] = A[M,K] @ B[N,K]^T  via bf16x3 split, fp32 accum.
// Block tile 128x128, K-chunk 32, 256 threads (2x4 warps, 64x32 warp tile),
// cp.async double-buffered smem, rows padded to 40 halves (conflict-free).
// M must be a multiple of 128; N ragged (B zero-filled, C stores guarded).
// ============================================================================
#define ROW_H 40                         // halves per smem row (32 data + 8 pad)
#define PLANE (128 * ROW_H * 2)          // 10240 B
#define OFF_AH 0
#define OFF_AL (PLANE)
#define OFF_BH (2 * PLANE)
#define OFF_BL (3 * PLANE)
#define STAGE  (4 * PLANE)               // 40960 B
#define GEMM_SMEM (2 * STAGE)            // 81920 B

__global__ void __launch_bounds__(256, 2) k_gemm(
    const __nv_bfloat16* __restrict__ Ahi, const __nv_bfloat16* __restrict__ Alo,
    const __nv_bfloat16* __restrict__ Bhi, const __nv_bfloat16* __restrict__ Blo,
    float* __restrict__ C, int K, int Nact, int ldc, int beta)
{
    extern __shared__ char smem[];
    const uint32_t sb = smem_u32(smem);
    const int tid  = threadIdx.x;
    const int lane = tid & 31;
    const int warp = tid >> 5;
    const int wm   = warp >> 2;          // 0..1
    const int wn   = warp & 3;           // 0..3
    const int bm   = blockIdx.y * 128;
    const int bn   = blockIdx.x * 128;
    const int nch  = K >> 5;

    float acc[4][4][4];
#pragma unroll
    for (int i = 0; i < 4; i++)
#pragma unroll
        for (int j = 0; j < 4; j++)
#pragma unroll
            for (int k = 0; k < 4; k++) acc[i][j][k] = 0.f;

    // ---- chunk loader: 512 16B vectors per plane, 2 iters x 4 planes/thread
    auto load_chunk = [&](int c, int s) {
        const int k0 = c << 5;
        const uint32_t st = sb + s * STAGE;
#pragma unroll
        for (int it = 0; it < 2; ++it) {
            const int i   = tid + it * 256;
            const int row = i >> 2;
            const int c8  = (i & 3) * 8;
            const uint32_t so = (uint32_t)(row * ROW_H + c8) * 2;
            const size_t ga = (size_t)(bm + row) * K + k0 + c8;
            cpa16(st + OFF_AH + so, Ahi + ga);
            cpa16(st + OFF_AL + so, Alo + ga);
            const size_t gb = (size_t)(bn + row) * K + k0 + c8;
            const int sz = (bn + row < Nact) ? 16 : 0;
            cpa16p(st + OFF_BH + so, Bhi + gb, sz);
            cpa16p(st + OFF_BL + so, Blo + gb, sz);
        }
    };

    load_chunk(0, 0);
    cp_commit();

    const uint32_t a_lane_off = (uint32_t)((lane & 15) * ROW_H + 8 * (lane >> 4)) * 2;
    const uint32_t b_lane_off = (uint32_t)((lane & 7) * ROW_H + 8 * ((lane >> 3) & 1)) * 2;

    for (int c = 0; c < nch; ++c) {
        if (c + 1 < nch) {
            load_chunk(c + 1, (c + 1) & 1);
            cp_commit();
            cp_wait<1>();
        } else {
            cp_wait<0>();
        }
        __syncthreads();

        const uint32_t st = sb + (c & 1) * STAGE;
#pragma unroll
        for (int k16 = 0; k16 < 32; k16 += 16) {
            const uint32_t ak = a_lane_off + k16 * 2;
            const uint32_t bk = b_lane_off + k16 * 2;
            uint32_t bh[4][2], bl[4][2];
#pragma unroll
            for (int j = 0; j < 4; ++j) {
                const uint32_t bo = (uint32_t)((wn * 32 + j * 8) * ROW_H) * 2 + bk;
                ldsm_x2(bh[j], st + OFF_BH + bo);
                ldsm_x2(bl[j], st + OFF_BL + bo);
            }
#pragma unroll
            for (int i = 0; i < 4; ++i) {
                const uint32_t ao = (uint32_t)((wm * 64 + i * 16) * ROW_H) * 2 + ak;
                uint32_t ah[4], al[4];
                ldsm_x4(ah, st + OFF_AH + ao);
                ldsm_x4(al, st + OFF_AL + ao);
#pragma unroll
                for (int j = 0; j < 4; ++j) {
                    mma_bf16(acc[i][j], ah, bh[j]);   // hi*hi
                    mma_bf16(acc[i][j], ah, bl[j]);   // hi*lo
                    mma_bf16(acc[i][j], al, bh[j]);   // lo*hi
                }
            }
        }
        __syncthreads();
    }

    // ---- epilogue: direct float2 stores
    const int gid = lane >> 2;
    const int tig = lane & 3;
#pragma unroll
    for (int i = 0; i < 4; ++i) {
        const int row = bm + wm * 64 + i * 16 + gid;
#pragma unroll
        for (int j = 0; j < 4; ++j) {
            const int col = bn + wn * 32 + j * 8 + tig * 2;
            if (col < Nact) {
                float2* p0 = (float2*)&C[(size_t)row * ldc + col];
                float2* p1 = (float2*)&C[(size_t)(row + 8) * ldc + col];
                float2 v0 = make_float2(acc[i][j][0], acc[i][j][1]);
                float2 v1 = make_float2(acc[i][j][2], acc[i][j][3]);
                if (beta) {
                    float2 o0 = *p0, o1 = *p1;
                    v0.x += o0.x; v0.y += o0.y; v1.x += o1.x; v1.y += o1.y;
                }
                *p0 = v0;
                *p1 = v1;
            }
        }
    }
}

// ============================================================================
// fp32 -> bf16 hi/lo conversion (contiguous, vectorized x4)
// ============================================================================
__global__ void k_cvt(const float4* __restrict__ src, __nv_bfloat16* __restrict__ hi,
                      __nv_bfloat16* __restrict__ lo, size_t n4) {
    size_t i = (size_t)blockIdx.x * blockDim.x + threadIdx.x;
    if (i >= n4) return;
    float4 v = src[i];
    __nv_bfloat16 h0, h1, h2, h3, l0, l1, l2, l3;
    split2(v.x, h0, l0); split2(v.y, h1, l1); split2(v.z, h2, l2); split2(v.w, h3, l3);
    __nv_bfloat162* H = (__nv_bfloat162*)hi;
    __nv_bfloat162* L = (__nv_bfloat162*)lo;
    H[2 * i]     = __nv_bfloat162(h0, h1);
    H[2 * i + 1] = __nv_bfloat162(h2, h3);
    L[2 * i]     = __nv_bfloat162(l0, l1);
    L[2 * i + 1] = __nv_bfloat162(l2, l3);
}

// dt_raw extraction: cols 0..63 of proj[., 96] per dir -> packed hi/lo [2*M*64]
__global__ void k_cvt_dtr() {
    size_t i4 = (size_t)blockIdx.x * blockDim.x + threadIdx.x;
    size_t total4 = (size_t)2 * M_ROWS * DR / 4;
    if (i4 >= total4) return;
    size_t i = i4 * 4;
    int col = (int)(i % DR);
    size_t r = i / DR;
    int row = (int)(r % M_ROWS);
    int dir = (int)(r / M_ROWS);
    const float* s = g_proj + (size_t)dir * M_ROWS * 96 + (size_t)row * 96 + col;
    float4 v = *(const float4*)s;
    __nv_bfloat16 h0, h1, h2, h3, l0, l1, l2, l3;
    split2(v.x, h0, l0); split2(v.y, h1, l1); split2(v.z, h2, l2); split2(v.w, h3, l3);
    __nv_bfloat162* H = (__nv_bfloat162*)g_dtr_hi;
    __nv_bfloat162* L = (__nv_bfloat162*)g_dtr_lo;
    H[2 * i4]     = __nv_bfloat162(h0, h1);
    H[2 * i4 + 1] = __nv_bfloat162(h2, h3);
    L[2 * i4]     = __nv_bfloat162(l0, l1);
    L[2 * i4 + 1] = __nv_bfloat162(l2, l3);
}

// ============================================================================
// Depthwise conv (causal fwd / anti-causal bwd) + SiLU -> xc hi/lo planes
// ============================================================================
__global__ void k_conv(const float* __restrict__ cw, const float* __restrict__ cb) {
    size_t idx = (size_t)blockIdx.x * blockDim.x + threadIdx.x;
    if (idx >= (size_t)2 * M_ROWS * DI) return;
    int e = (int)(idx % DI);
    size_t r = idx / DI;
    int m = (int)(r % M_ROWS);
    int dir = (int)(r / M_ROWS);
    int l = m % L_SEQ;
    int b = m / L_SEQ;

    float acc = cb[dir * DI + e];
    const float* w4 = cw + ((size_t)dir * DI + e) * 4;
#pragma unroll
    for (int k = 0; k < 4; k++) {
        int tl = (dir == 0) ? (l - 3 + k) : (l + 3 - k);
        if (tl >= 0 && tl < L_SEQ)
            acc = fmaf(w4[k], g_xz[((size_t)(b * L_SEQ + tl)) * 8192 + dir * 4096 + e], acc);
    }
    float xc = acc / (1.f + __expf(-acc));   // silu
    __nv_bfloat16 h, lo;
    split2(xc, h, lo);
    size_t o = ((size_t)dir * M_ROWS + m) * DI + e;
    g_xc_hi[o] = h;
    g_xc_lo[o] = lo;
}

// ============================================================================
// Selective scan: 128-thread blocks (4 warps -> 4 SMSPs), per-warp B/C smem,
// next-timestep register prefetch. Fuses softplus, recurrence, D-skip, gating.
// ============================================================================
__global__ void __launch_bounds__(128) k_scan(const float* __restrict__ dt_b,
                                              const float* __restrict__ A_log,
                                              const float* __restrict__ Dp) {
    const int tid  = threadIdx.x;
    const int lane = tid & 31;
    const int warp = tid >> 5;
    const int dir  = blockIdx.z;
    const int b    = blockIdx.y;
    const int e    = blockIdx.x * 128 + tid;

    __shared__ float sB[4][16], sC[4][16];

    float a[16];
#pragma unroll
    for (int s = 0; s < 16; s++)
        a[s] = -__expf(A_log[((size_t)dir * DI + e) * 16 + s]);

    const float bias  = dt_b[dir * DI + e];
    const float dcoef = Dp[dir * DI + e];

    float h[16];
#pragma unroll
    for (int s = 0; s < 16; s++) h[s] = 0.f;

    const size_t base_de   = (size_t)dir * M_ROWS * DI;
    const size_t proj_base = (size_t)dir * M_ROWS * 96;

    // prefetch t = 0
    int tt0 = dir ? (L_SEQ - 1) : 0;
    size_t m_n = (size_t)b * L_SEQ + tt0;
    float bc_n = g_proj[proj_base + m_n * 96 + 64 + lane];
    float dt_n = g_dt[base_de + m_n * DI + e];
    float xh_n = __bfloat162float(g_xc_hi[base_de + m_n * DI + e]);
    float xl_n = __bfloat162float(g_xc_lo[base_de + m_n * DI + e]);
    float z_n  = g_xz[m_n * 8192 + dir * 4096 + 2048 + e];

    for (int t = 0; t < L_SEQ; t++) {
        const size_t m = m_n;
        const float bc = bc_n, dtv = dt_n, xh = xh_n, xl = xl_n, zz = z_n;

        if (t + 1 < L_SEQ) {
            const int tt = dir ? (L_SEQ - 2 - t) : (t + 1);
            m_n  = (size_t)b * L_SEQ + tt;
            bc_n = g_proj[proj_base + m_n * 96 + 64 + lane];
            dt_n = g_dt[base_de + m_n * DI + e];
            xh_n = __bfloat162float(g_xc_hi[base_de + m_n * DI + e]);
            xl_n = __bfloat162float(g_xc_lo[base_de + m_n * DI + e]);
            z_n  = g_xz[m_n * 8192 + dir * 4096 + 2048 + e];
        }

        if (lane < 16) sB[warp][lane] = bc; else sC[warp][lane - 16] = bc;
        __syncwarp();

        const float v  = dtv + bias;
        const float dt = (v > 15.f) ? v : log1pf(__expf(v));
        const float x  = xh + xl;
        const float dtx = dt * x;

        float y = 0.f;
#pragma unroll
        for (int s = 0; s < 16; s++) {
            float dA = __expf(dt * a[s]);
            h[s] = fmaf(h[s], dA, dtx * sB[warp][s]);
            y    = fmaf(h[s], sC[warp][s], y);
        }
        const float yv = fmaf(x, dcoef, y);
        const float sz = zz / (1.f + __expf(-zz));
        const float out = yv * sz;
        __nv_bfloat16 hh, ll;
        split2(out, hh, ll);
        const size_t o = base_de + m * DI + e;
        g_y_hi[o] = hh;
        g_y_lo[o] = ll;
        __syncwarp();
    }
}

// ============================================================================
extern "C" void kernel_launch(void* const* d_in, const int* in_sizes, int n_in,
                              void* d_out, int out_size) {
    const float* x      = (const float*)d_in[0];
    const float* in_w   = (const float*)d_in[1];
    const float* conv_w = (const float*)d_in[2];
    const float* conv_b = (const float*)d_in[3];
    const float* x_w    = (const float*)d_in[4];
    const float* dt_w   = (const float*)d_in[5];
    const float* dt_bv  = (const float*)d_in[6];
    const float* A_log  = (const float*)d_in[7];
    const float* Dp     = (const float*)d_in[8];
    const float* out_w  = (const float*)d_in[9];
    float* out = (float*)d_out;

    cudaFuncSetAttribute(k_gemm, cudaFuncAttributeMaxDynamicSharedMemorySize, GEMM_SMEM);

    float *xz, *proj, *dtv;
    __nv_bfloat16 *xhi, *xlo, *inwhi, *inwlo, *xwhi, *xwlo, *dtwhi, *dtwlo, *owhi, *owlo;
    __nv_bfloat16 *xchi, *xclo, *dtrhi, *dtrlo, *yhi, *ylo;
    cudaGetSymbolAddress((void**)&xz, g_xz);
    cudaGetSymbolAddress((void**)&proj, g_proj);
    cudaGetSymbolAddress((void**)&dtv, g_dt);
    cudaGetSymbolAddress((void**)&xhi, g_x_hi);     cudaGetSymbolAddress((void**)&xlo, g_x_lo);
    cudaGetSymbolAddress((void**)&inwhi, g_inw_hi); cudaGetSymbolAddress((void**)&inwlo, g_inw_lo);
    cudaGetSymbolAddress((void**)&xwhi, g_xw_hi);   cudaGetSymbolAddress((void**)&xwlo, g_xw_lo);
    cudaGetSymbolAddress((void**)&dtwhi, g_dtw_hi); cudaGetSymbolAddress((void**)&dtwlo, g_dtw_lo);
    cudaGetSymbolAddress((void**)&owhi, g_ow_hi);   cudaGetSymbolAddress((void**)&owlo, g_ow_lo);
    cudaGetSymbolAddress((void**)&xchi, g_xc_hi);   cudaGetSymbolAddress((void**)&xclo, g_xc_lo);
    cudaGetSymbolAddress((void**)&dtrhi, g_dtr_hi); cudaGetSymbolAddress((void**)&dtrlo, g_dtr_lo);
    cudaGetSymbolAddress((void**)&yhi, g_y_hi);     cudaGetSymbolAddress((void**)&ylo, g_y_lo);

    // 1) fp32 -> bf16 hi/lo planes
    auto cvt = [&](const float* src, __nv_bfloat16* hi, __nv_bfloat16* lo, size_t n) {
        size_t n4 = n / 4;
        k_cvt<<<(unsigned)((n4 + 255) / 256), 256>>>((const float4*)src, hi, lo, n4);
    };
    cvt(x,     xhi,   xlo,   (size_t)M_ROWS * DM);
    cvt(in_w,  inwhi, inwlo, (size_t)8192 * DM);
    cvt(x_w,   xwhi,  xwlo,  (size_t)2 * 96 * DI);
    cvt(dt_w,  dtwhi, dtwlo, (size_t)2 * DI * DR);
    cvt(out_w, owhi,  owlo,  (size_t)2 * DM * DI);

    // 2) in_proj: xz = x @ in_w^T  (M=8192, N=8192, K=1024)
    k_gemm<<<dim3(64, 64), 256, GEMM_SMEM>>>(xhi, xlo, inwhi, inwlo, xz, DM, 8192, 8192, 0);

    // 3) depthwise conv + silu -> xc hi/lo
    k_conv<<<(unsigned)(((size_t)2 * M_ROWS * DI) / 256), 256>>>(conv_w, conv_b);

    // 4) x_proj per dir: proj = xc @ x_proj_w^T (N=96, K=2048)
    for (int d = 0; d < 2; d++)
        k_gemm<<<dim3(1, 64), 256, GEMM_SMEM>>>(
            xchi + (size_t)d * M_ROWS * DI, xclo + (size_t)d * M_ROWS * DI,
            xwhi + (size_t)d * 96 * DI,     xwlo + (size_t)d * 96 * DI,
            proj + (size_t)d * M_ROWS * 96, DI, 96, 96, 0);

    // 5) extract + convert dt_raw
    {
        size_t n4 = (size_t)2 * M_ROWS * DR / 4;
        k_cvt_dtr<<<(unsigned)((n4 + 255) / 256), 256>>>();
    }

    // 6) dt_proj per dir: dt = dt_raw @ dt_proj_w^T (N=2048, K=64)
    for (int d = 0; d < 2; d++)
        k_gemm<<<dim3(16, 64), 256, GEMM_SMEM>>>(
            dtrhi + (size_t)d * M_ROWS * DR, dtrlo + (size_t)d * M_ROWS * DR,
            dtwhi + (size_t)d * DI * DR,     dtwlo + (size_t)d * DI * DR,
            dtv + (size_t)d * M_ROWS * DI, DR, DI, DI, 0);

    // 7) selective scan + gating -> y hi/lo
    k_scan<<<dim3(DI / 128, BSZ, 2), 128>>>(dt_bv, A_log, Dp);

    // 8) out_proj: out = y0 @ ow0^T ; out += y1 @ ow1^T
    for (int d = 0; d < 2; d++)
        k_gemm<<<dim3(8, 64), 256, GEMM_SMEM>>>(
            yhi + (size_t)d * M_ROWS * DI, ylo + (size_t)d * M_ROWS * DI,
            owhi + (size_t)d * DM * DI,    owlo + (size_t)d * DM * DI,
            out, DI, DM, DM, d /* beta */);
}

// round 4
// speedup vs baseline: 2.4659x; 1.0460x over previous
#include <cuda_runtime.h>
#include <cuda_bf16.h>
#include <cstdint>
#include <math.h>

// Problem dims
#define L_SEQ 2048
#define BSZ   4
#define DM    1024
#define DI    2048
#define DS    16
#define DR    64
#define M_ROWS 8192   // BSZ * L_SEQ

// ============================================================================
// Scratch (static device arrays)
// ============================================================================
__device__ float g_xz  [(size_t)M_ROWS * 8192];             // in_proj output (xi|z per dir)
__device__ float g_proj[2 * (size_t)M_ROWS * 96];           // x_proj output (dt_raw|B|C)
__device__ float g_dt  [2 * (size_t)M_ROWS * DI];           // dt_proj output (pre-softplus)

// bf16 hi/lo operand planes
__device__ __nv_bfloat16 g_x_hi  [(size_t)M_ROWS * DM],  g_x_lo  [(size_t)M_ROWS * DM];
__device__ __nv_bfloat16 g_inw_hi[(size_t)8192 * DM],    g_inw_lo[(size_t)8192 * DM];
__device__ __nv_bfloat16 g_xw_hi [2 * 96 * (size_t)DI],  g_xw_lo [2 * 96 * (size_t)DI];
__device__ __nv_bfloat16 g_dtw_hi[2 * (size_t)DI * DR],  g_dtw_lo[2 * (size_t)DI * DR];
__device__ __nv_bfloat16 g_ow_hi [2 * (size_t)DM * DI],  g_ow_lo [2 * (size_t)DM * DI];
__device__ __nv_bfloat16 g_xc_hi [2 * (size_t)M_ROWS * DI], g_xc_lo[2 * (size_t)M_ROWS * DI];
__device__ __nv_bfloat16 g_dtr_hi[2 * (size_t)M_ROWS * DR], g_dtr_lo[2 * (size_t)M_ROWS * DR];
__device__ __nv_bfloat16 g_y_hi  [2 * (size_t)M_ROWS * DI], g_y_lo [2 * (size_t)M_ROWS * DI];

__device__ __forceinline__ void split2(float v, __nv_bfloat16& h, __nv_bfloat16& l) {
    h = __float2bfloat16_rn(v);
    l = __float2bfloat16_rn(v - __bfloat162float(h));
}

// ============================================================================
// PTX helpers (sm_80-class only: valid on base sm_103 target)
// ============================================================================
__device__ __forceinline__ uint32_t smem_u32(const void* p) {
    uint32_t a;
    asm("{ .reg .u64 t; cvta.to.shared.u64 t, %1; cvt.u32.u64 %0, t; }" : "=r"(a) : "l"(p));
    return a;
}
__device__ __forceinline__ void cpa16(uint32_t dst, const void* src) {
    asm volatile("cp.async.cg.shared.global [%0], [%1], 16;" :: "r"(dst), "l"(src) : "memory");
}
__device__ __forceinline__ void cpa16p(uint32_t dst, const void* src, int sz) {
    asm volatile("cp.async.cg.shared.global [%0], [%1], 16, %2;" :: "r"(dst), "l"(src), "r"(sz) : "memory");
}
__device__ __forceinline__ void cp_commit() {
    asm volatile("cp.async.commit_group;" ::: "memory");
}
template <int N>
__device__ __forceinline__ void cp_wait() {
    asm volatile("cp.async.wait_group %0;" :: "n"(N) : "memory");
}
__device__ __forceinline__ void ldsm_x4(uint32_t* r, uint32_t addr) {
    asm volatile("ldmatrix.sync.aligned.m8n8.x4.shared.b16 {%0,%1,%2,%3}, [%4];"
                 : "=r"(r[0]), "=r"(r[1]), "=r"(r[2]), "=r"(r[3]) : "r"(addr));
}
__device__ __forceinline__ void ldsm_x2(uint32_t* r, uint32_t addr) {
    asm volatile("ldmatrix.sync.aligned.m8n8.x2.shared.b16 {%0,%1}, [%2];"
                 : "=r"(r[0]), "=r"(r[1]) : "r"(addr));
}
__device__ __forceinline__ void mma_bf16(float* d, const uint32_t* a, const uint32_t* b) {
    asm volatile("mma.sync.aligned.m16n8k16.row.col.f32.bf16.bf16.f32 "
                 "{%0,%1,%2,%3}, {%4,%5,%6,%7}, {%8,%9}, {%0,%1,%2,%3};"
                 : "+f"(d[0]), "+f"(d[1]), "+f"(d[2]), "+f"(d[3])
                 : "r"(a[0]), "r"(a[1]), "r"(a[2]), "r"(a[3]), "r"(b[0]), "r"(b[1]));
}

// ============================================================================
// Shared GEMM machinery: 128x128 tile, K-chunk 32, 256 threads (2x4 warps,
// 64x32 warp tiles), cp.async double-buffered smem, rows padded to 40 halves.
// bf16x3 split: acc += Ah*Bh + Ah*Bl + Al*Bh  (fp32 accumulate)
// ============================================================================
#define ROW_H 40
#define PLANE (128 * ROW_H * 2)          // 10240 B
#define OFF_AH 0
#define OFF_AL (PLANE)
#define OFF_BH (2 * PLANE)
#define OFF_BL (3 * PLANE)
#define STAGE  (4 * PLANE)               // 40960 B
#define GEMM_SMEM (2 * STAGE)            // 81920 B

struct GemmCtx {
    uint32_t sb;
    int tid, lane, warp, wm, wn, bm, bn;
    uint32_t a_lane_off, b_lane_off;
};

__device__ __forceinline__ void gemm_init(GemmCtx& g, char* smem) {
    g.sb = smem_u32(smem);
    g.tid = threadIdx.x;
    g.lane = g.tid & 31;
    g.warp = g.tid >> 5;
    g.wm = g.warp >> 2;
    g.wn = g.warp & 3;
    g.bm = blockIdx.y * 128;
    g.bn = blockIdx.x * 128;
    g.a_lane_off = (uint32_t)((g.lane & 15) * ROW_H + 8 * (g.lane >> 4)) * 2;
    g.b_lane_off = (uint32_t)((g.lane & 7) * ROW_H + 8 * ((g.lane >> 3) & 1)) * 2;
}

__device__ __forceinline__ void gemm_load_chunk(
    const GemmCtx& g, int s, int k0, int K,
    const __nv_bfloat16* __restrict__ Ahi, const __nv_bfloat16* __restrict__ Alo,
    const __nv_bfloat16* __restrict__ Bhi, const __nv_bfloat16* __restrict__ Blo,
    int Nact)
{
    const uint32_t st = g.sb + s * STAGE;
#pragma unroll
    for (int it = 0; it < 2; ++it) {
        const int i   = g.tid + it * 256;
        const int row = i >> 2;
        const int c8  = (i & 3) * 8;
        const uint32_t so = (uint32_t)(row * ROW_H + c8) * 2;
        const size_t ga = (size_t)(g.bm + row) * K + k0 + c8;
        cpa16(st + OFF_AH + so, Ahi + ga);
        cpa16(st + OFF_AL + so, Alo + ga);
        const size_t gb = (size_t)(g.bn + row) * K + k0 + c8;
        const int sz = (g.bn + row < Nact) ? 16 : 0;
        cpa16p(st + OFF_BH + so, Bhi + gb, sz);
        cpa16p(st + OFF_BL + so, Blo + gb, sz);
    }
}

__device__ __forceinline__ void gemm_compute_chunk(const GemmCtx& g, int s, float acc[4][4][4]) {
    const uint32_t st = g.sb + s * STAGE;
#pragma unroll
    for (int k16 = 0; k16 < 32; k16 += 16) {
        const uint32_t ak = g.a_lane_off + k16 * 2;
        const uint32_t bk = g.b_lane_off + k16 * 2;
        uint32_t bh[4][2], bl[4][2];
#pragma unroll
        for (int j = 0; j < 4; ++j) {
            const uint32_t bo = (uint32_t)((g.wn * 32 + j * 8) * ROW_H) * 2 + bk;
            ldsm_x2(bh[j], st + OFF_BH + bo);
            ldsm_x2(bl[j], st + OFF_BL + bo);
        }
#pragma unroll
        for (int i = 0; i < 4; ++i) {
            const uint32_t ao = (uint32_t)((g.wm * 64 + i * 16) * ROW_H) * 2 + ak;
            uint32_t ah[4], al[4];
            ldsm_x4(ah, st + OFF_AH + ao);
            ldsm_x4(al, st + OFF_AL + ao);
#pragma unroll
            for (int j = 0; j < 4; ++j) {
                mma_bf16(acc[i][j], ah, bh[j]);
                mma_bf16(acc[i][j], ah, bl[j]);
                mma_bf16(acc[i][j], al, bh[j]);
            }
        }
    }
}

// ============================================================================
// k_gemm_z: C[z][M,N] = A[z][M,K] @ B[z][N,K]^T   (z = blockIdx.z, strides)
// Optional dtr epilogue: cols<64 also split to g_dtr_hi/lo (x_proj only).
// ============================================================================
__global__ void __launch_bounds__(256, 2) k_gemm_z(
    const __nv_bfloat16* __restrict__ Ahi, const __nv_bfloat16* __restrict__ Alo, size_t aStride,
    const __nv_bfloat16* __restrict__ Bhi, const __nv_bfloat16* __restrict__ Blo, size_t bStride,
    float* __restrict__ C, size_t cStride, int K, int Nact, int ldc, int doDtr)
{
    extern __shared__ char smem[];
    GemmCtx g;
    gemm_init(g, smem);
    const int z = blockIdx.z;
    Ahi += (size_t)z * aStride; Alo += (size_t)z * aStride;
    Bhi += (size_t)z * bStride; Blo += (size_t)z * bStride;
    C   += (size_t)z * cStride;
    const int nch = K >> 5;

    float acc[4][4][4];
#pragma unroll
    for (int i = 0; i < 4; i++)
#pragma unroll
        for (int j = 0; j < 4; j++)
#pragma unroll
            for (int k = 0; k < 4; k++) acc[i][j][k] = 0.f;

    gemm_load_chunk(g, 0, 0, K, Ahi, Alo, Bhi, Blo, Nact);
    cp_commit();

    for (int c = 0; c < nch; ++c) {
        if (c + 1 < nch) {
            gemm_load_chunk(g, (c + 1) & 1, (c + 1) << 5, K, Ahi, Alo, Bhi, Blo, Nact);
            cp_commit();
            cp_wait<1>();
        } else {
            cp_wait<0>();
        }
        __syncthreads();
        gemm_compute_chunk(g, c & 1, acc);
        __syncthreads();
    }

    const int gid = g.lane >> 2;
    const int tig = g.lane & 3;
#pragma unroll
    for (int i = 0; i < 4; ++i) {
        const int row = g.bm + g.wm * 64 + i * 16 + gid;
#pragma unroll
        for (int j = 0; j < 4; ++j) {
            const int col = g.bn + g.wn * 32 + j * 8 + tig * 2;
            if (col < Nact) {
                *(float2*)&C[(size_t)row * ldc + col]       = make_float2(acc[i][j][0], acc[i][j][1]);
                *(float2*)&C[(size_t)(row + 8) * ldc + col] = make_float2(acc[i][j][2], acc[i][j][3]);
                if (doDtr && col < DR) {
                    __nv_bfloat16 h0, l0, h1, l1;
                    size_t d0 = ((size_t)z * M_ROWS + row) * DR + col;
                    split2(acc[i][j][0], h0, l0); split2(acc[i][j][1], h1, l1);
                    g_dtr_hi[d0] = h0; g_dtr_hi[d0 + 1] = h1;
                    g_dtr_lo[d0] = l0; g_dtr_lo[d0 + 1] = l1;
                    size_t d8 = d0 + 8 * DR;
                    split2(acc[i][j][2], h0, l0); split2(acc[i][j][3], h1, l1);
                    g_dtr_hi[d8] = h0; g_dtr_hi[d8 + 1] = h1;
                    g_dtr_lo[d8] = l0; g_dtr_lo[d8 + 1] = l1;
                }
            }
        }
    }
}

// ============================================================================
// k_gemm_cat: out = y0 @ ow0^T + y1 @ ow1^T  (K-concatenated, single pass)
// ============================================================================
__global__ void __launch_bounds__(256, 2) k_gemm_cat(
    const __nv_bfloat16* __restrict__ A0hi, const __nv_bfloat16* __restrict__ A0lo,
    const __nv_bfloat16* __restrict__ A1hi, const __nv_bfloat16* __restrict__ A1lo,
    const __nv_bfloat16* __restrict__ B0hi, const __nv_bfloat16* __restrict__ B0lo,
    const __nv_bfloat16* __restrict__ B1hi, const __nv_bfloat16* __restrict__ B1lo,
    float* __restrict__ C, int Kh, int Nact, int ldc)
{
    extern __shared__ char smem[];
    GemmCtx g;
    gemm_init(g, smem);
    const int nch_h = Kh >> 5;       // chunks per half
    const int nch = nch_h * 2;

    float acc[4][4][4];
#pragma unroll
    for (int i = 0; i < 4; i++)
#pragma unroll
        for (int j = 0; j < 4; j++)
#pragma unroll
            for (int k = 0; k < 4; k++) acc[i][j][k] = 0.f;

    auto load = [&](int c, int s) {
        if (c < nch_h)
            gemm_load_chunk(g, s, c << 5, Kh, A0hi, A0lo, B0hi, B0lo, Nact);
        else
            gemm_load_chunk(g, s, (c - nch_h) << 5, Kh, A1hi, A1lo, B1hi, B1lo, Nact);
    };

    load(0, 0);
    cp_commit();
    for (int c = 0; c < nch; ++c) {
        if (c + 1 < nch) {
            load(c + 1, (c + 1) & 1);
            cp_commit();
            cp_wait<1>();
        } else {
            cp_wait<0>();
        }
        __syncthreads();
        gemm_compute_chunk(g, c & 1, acc);
        __syncthreads();
    }

    const int gid = g.lane >> 2;
    const int tig = g.lane & 3;
#pragma unroll
    for (int i = 0; i < 4; ++i) {
        const int row = g.bm + g.wm * 64 + i * 16 + gid;
#pragma unroll
        for (int j = 0; j < 4; ++j) {
            const int col = g.bn + g.wn * 32 + j * 8 + tig * 2;
            if (col < Nact) {
                *(float2*)&C[(size_t)row * ldc + col]       = make_float2(acc[i][j][0], acc[i][j][1]);
                *(float2*)&C[(size_t)(row + 8) * ldc + col] = make_float2(acc[i][j][2], acc[i][j][3]);
            }
        }
    }
}

// ============================================================================
// Fused fp32 -> bf16 hi/lo conversion for all 5 input tensors (one launch)
// ============================================================================
#define N4_X   2097152u   // 8192*1024/4
#define N4_INW 2097152u   // 8192*1024/4
#define N4_XW  98304u     // 2*96*2048/4
#define N4_DTW 65536u     // 2*2048*64/4
#define N4_OW  1048576u   // 2*1024*2048/4
#define N4_TOT (N4_X + N4_INW + N4_XW + N4_DTW + N4_OW)

__global__ void k_cvt_all(const float4* __restrict__ x, const float4* __restrict__ inw,
                          const float4* __restrict__ xw, const float4* __restrict__ dtw,
                          const float4* __restrict__ ow) {
    uint32_t i = blockIdx.x * blockDim.x + threadIdx.x;
    if (i >= N4_TOT) return;
    const float4* src;
    __nv_bfloat16 *hi, *lo;
    uint32_t off = i;
    if (i < N4_X)                         { src = x;   hi = g_x_hi;   lo = g_x_lo; }
    else if ((off -= N4_X)   < N4_INW)    { src = inw; hi = g_inw_hi; lo = g_inw_lo; }
    else if ((off -= N4_INW) < N4_XW)     { src = xw;  hi = g_xw_hi;  lo = g_xw_lo; }
    else if ((off -= N4_XW)  < N4_DTW)    { src = dtw; hi = g_dtw_hi; lo = g_dtw_lo; }
    else { off -= N4_DTW;                   src = ow;  hi = g_ow_hi;  lo = g_ow_lo; }

    float4 v = src[off];
    __nv_bfloat16 h0, h1, h2, h3, l0, l1, l2, l3;
    split2(v.x, h0, l0); split2(v.y, h1, l1); split2(v.z, h2, l2); split2(v.w, h3, l3);
    __nv_bfloat162* H = (__nv_bfloat162*)hi;
    __nv_bfloat162* L = (__nv_bfloat162*)lo;
    H[2 * (size_t)off]     = __nv_bfloat162(h0, h1);
    H[2 * (size_t)off + 1] = __nv_bfloat162(h2, h3);
    L[2 * (size_t)off]     = __nv_bfloat162(l0, l1);
    L[2 * (size_t)off + 1] = __nv_bfloat162(l2, l3);
}

// ============================================================================
// Depthwise conv (causal fwd / anti-causal bwd) + SiLU -> xc hi/lo planes
// ============================================================================
__global__ void k_conv(const float* __restrict__ cw, const float* __restrict__ cb) {
    size_t idx = (size_t)blockIdx.x * blockDim.x + threadIdx.x;
    if (idx >= (size_t)2 * M_ROWS * DI) return;
    int e = (int)(idx % DI);
    size_t r = idx / DI;
    int m = (int)(r % M_ROWS);
    int dir = (int)(r / M_ROWS);
    int l = m % L_SEQ;
    int b = m / L_SEQ;

    float acc = cb[dir * DI + e];
    const float* w4 = cw + ((size_t)dir * DI + e) * 4;
#pragma unroll
    for (int k = 0; k < 4; k++) {
        int tl = (dir == 0) ? (l - 3 + k) : (l + 3 - k);
        if (tl >= 0 && tl < L_SEQ)
            acc = fmaf(w4[k], g_xz[((size_t)(b * L_SEQ + tl)) * 8192 + dir * 4096 + e], acc);
    }
    float xc = acc / (1.f + __expf(-acc));   // silu
    __nv_bfloat16 h, lo;
    split2(xc, h, lo);
    size_t o = ((size_t)dir * M_ROWS + m) * DI + e;
    g_xc_hi[o] = h;
    g_xc_lo[o] = lo;
}

// ============================================================================
// Selective scan: 128-thread blocks (4 warps -> 4 SMSPs), 4-deep register-ring
// prefetch on all 5 input streams. Fuses softplus, recurrence, D-skip, gating.
// ============================================================================
__global__ void __launch_bounds__(128) k_scan(const float* __restrict__ dt_b,
                                              const float* __restrict__ A_log,
                                              const float* __restrict__ Dp) {
    const int tid  = threadIdx.x;
    const int lane = tid & 31;
    const int warp = tid >> 5;
    const int dir  = blockIdx.z;
    const int b    = blockIdx.y;
    const int e    = blockIdx.x * 128 + tid;

    __shared__ float sB[4][16], sC[4][16];

    float a[16];
#pragma unroll
    for (int s = 0; s < 16; s++)
        a[s] = -__expf(A_log[((size_t)dir * DI + e) * 16 + s]);

    const float bias  = dt_b[dir * DI + e];
    const float dcoef = Dp[dir * DI + e];

    float h[16];
#pragma unroll
    for (int s = 0; s < 16; s++) h[s] = 0.f;

    const size_t base_de   = (size_t)dir * M_ROWS * DI;
    const size_t proj_base = (size_t)dir * M_ROWS * 96;
    const size_t brow      = (size_t)b * L_SEQ;

    // 4-deep prefetch ring
    float rbc[4], rdt[4], rxh[4], rxl[4], rz[4];
#pragma unroll
    for (int p = 0; p < 4; p++) {
        const int tt = dir ? (L_SEQ - 1 - p) : p;
        const size_t m = brow + tt;
        rbc[p] = g_proj[proj_base + m * 96 + 64 + lane];
        rdt[p] = g_dt[base_de + m * DI + e];
        rxh[p] = __bfloat162float(g_xc_hi[base_de + m * DI + e]);
        rxl[p] = __bfloat162float(g_xc_lo[base_de + m * DI + e]);
        rz[p]  = g_xz[m * 8192 + dir * 4096 + 2048 + e];
    }

    for (int t0 = 0; t0 < L_SEQ; t0 += 4) {
#pragma unroll
        for (int u = 0; u < 4; u++) {
            const int t  = t0 + u;
            const int tt = dir ? (L_SEQ - 1 - t) : t;
            const size_t m = brow + tt;

            const float bc = rbc[u], dtv = rdt[u], xh = rxh[u], xl = rxl[u], zz = rz[u];

            // prefetch t+4 into the just-freed slot (overlaps with compute)
            const int tp = t + 4;
            if (tp < L_SEQ) {
                const int tq = dir ? (L_SEQ - 1 - tp) : tp;
                const size_t mp = brow + tq;
                rbc[u] = g_proj[proj_base + mp * 96 + 64 + lane];
                rdt[u] = g_dt[base_de + mp * DI + e];
                rxh[u] = __bfloat162float(g_xc_hi[base_de + mp * DI + e]);
                rxl[u] = __bfloat162float(g_xc_lo[base_de + mp * DI + e]);
                rz[u]  = g_xz[mp * 8192 + dir * 4096 + 2048 + e];
            }

            if (lane < 16) sB[warp][lane] = bc; else sC[warp][lane - 16] = bc;
            __syncwarp();

            const float v   = dtv + bias;
            const float dt  = (v > 15.f) ? v : log1pf(__expf(v));
            const float x   = xh + xl;
            const float dtx = dt * x;

            float y = 0.f;
#pragma unroll
            for (int s = 0; s < 16; s++) {
                float dA = __expf(dt * a[s]);
                h[s] = fmaf(h[s], dA, dtx * sB[warp][s]);
                y    = fmaf(h[s], sC[warp][s], y);
            }
            const float yv  = fmaf(x, dcoef, y);
            const float sz  = zz / (1.f + __expf(-zz));
            const float out = yv * sz;
            __nv_bfloat16 hh, ll;
            split2(out, hh, ll);
            const size_t o = base_de + m * DI + e;
            g_y_hi[o] = hh;
            g_y_lo[o] = ll;
            __syncwarp();
        }
    }
}

// ============================================================================
extern "C" void kernel_launch(void* const* d_in, const int* in_sizes, int n_in,
                              void* d_out, int out_size) {
    const float* x      = (const float*)d_in[0];
    const float* in_w   = (const float*)d_in[1];
    const float* conv_w = (const float*)d_in[2];
    const float* conv_b = (const float*)d_in[3];
    const float* x_w    = (const float*)d_in[4];
    const float* dt_w   = (const float*)d_in[5];
    const float* dt_bv  = (const float*)d_in[6];
    const float* A_log  = (const float*)d_in[7];
    const float* Dp     = (const float*)d_in[8];
    const float* out_w  = (const float*)d_in[9];
    float* out = (float*)d_out;

    cudaFuncSetAttribute(k_gemm_z,   cudaFuncAttributeMaxDynamicSharedMemorySize, GEMM_SMEM);
    cudaFuncSetAttribute(k_gemm_cat, cudaFuncAttributeMaxDynamicSharedMemorySize, GEMM_SMEM);

    float *xz, *proj, *dtv;
    __nv_bfloat16 *xhi, *xlo, *inwhi, *inwlo, *xwhi, *xwlo, *dtwhi, *dtwlo, *owhi, *owlo;
    __nv_bfloat16 *xchi, *xclo, *dtrhi, *dtrlo, *yhi, *ylo;
    cudaGetSymbolAddress((void**)&xz, g_xz);
    cudaGetSymbolAddress((void**)&proj, g_proj);
    cudaGetSymbolAddress((void**)&dtv, g_dt);
    cudaGetSymbolAddress((void**)&xhi, g_x_hi);     cudaGetSymbolAddress((void**)&xlo, g_x_lo);
    cudaGetSymbolAddress((void**)&inwhi, g_inw_hi); cudaGetSymbolAddress((void**)&inwlo, g_inw_lo);
    cudaGetSymbolAddress((void**)&xwhi, g_xw_hi);   cudaGetSymbolAddress((void**)&xwlo, g_xw_lo);
    cudaGetSymbolAddress((void**)&dtwhi, g_dtw_hi); cudaGetSymbolAddress((void**)&dtwlo, g_dtw_lo);
    cudaGetSymbolAddress((void**)&owhi, g_ow_hi);   cudaGetSymbolAddress((void**)&owlo, g_ow_lo);
    cudaGetSymbolAddress((void**)&xchi, g_xc_hi);   cudaGetSymbolAddress((void**)&xclo, g_xc_lo);
    cudaGetSymbolAddress((void**)&dtrhi, g_dtr_hi); cudaGetSymbolAddress((void**)&dtrlo, g_dtr_lo);
    cudaGetSymbolAddress((void**)&yhi, g_y_hi);     cudaGetSymbolAddress((void**)&ylo, g_y_lo);

    // 0) all fp32 -> bf16 hi/lo conversions, one launch
    k_cvt_all<<<(N4_TOT + 255) / 256, 256>>>((const float4*)x, (const float4*)in_w,
                                             (const float4*)x_w, (const float4*)dt_w,
                                             (const float4*)out_w);

    // 1) in_proj: xz = x @ in_w^T  (M=8192, N=8192, K=1024)
    k_gemm_z<<<dim3(64, 64, 1), 256, GEMM_SMEM>>>(xhi, xlo, 0, inwhi, inwlo, 0,
                                                  xz, 0, DM, 8192, 8192, 0);

    // 2) depthwise conv + silu -> xc hi/lo
    k_conv<<<(unsigned)(((size_t)2 * M_ROWS * DI) / 256), 256>>>(conv_w, conv_b);

    // 3) x_proj (both dirs): proj = xc @ x_proj_w^T (N=96, K=2048); dtr fused
    k_gemm_z<<<dim3(1, 64, 2), 256, GEMM_SMEM>>>(
        xchi, xclo, (size_t)M_ROWS * DI, xwhi, xwlo, (size_t)96 * DI,
        proj, (size_t)M_ROWS * 96, DI, 96, 96, 1);

    // 4) dt_proj (both dirs): dt = dt_raw @ dt_proj_w^T (N=2048, K=64)
    k_gemm_z<<<dim3(16, 64, 2), 256, GEMM_SMEM>>>(
        dtrhi, dtrlo, (size_t)M_ROWS * DR, dtwhi, dtwlo, (size_t)DI * DR,
        dtv, (size_t)M_ROWS * DI, DR, DI, DI, 0);

    // 5) selective scan + gating -> y hi/lo
    k_scan<<<dim3(DI / 128, BSZ, 2), 128>>>(dt_bv, A_log, Dp);

    // 6) out_proj (both dirs, K-concatenated single pass)
    k_gemm_cat<<<dim3(8, 64, 1), 256, GEMM_SMEM>>>(
        yhi, ylo, yhi + (size_t)M_ROWS * DI, ylo + (size_t)M_ROWS * DI,
        owhi, owlo, owhi + (size_t)DM * DI, owlo + (size_t)DM * DI,
        out, DI, DM, DM);
}

// round 5
// speedup vs baseline: 2.4901x; 1.0098x over previous
#include <cuda_runtime.h>
#include <cuda_bf16.h>
#include <cstdint>
#include <math.h>

// Problem dims
#define L_SEQ 2048
#define BSZ   4
#define DM    1024
#define DI    2048
#define DS    16
#define DR    64
#define M_ROWS 8192   // BSZ * L_SEQ

// ============================================================================
// Scratch (static device arrays)
// ============================================================================
__device__ float g_xz  [(size_t)M_ROWS * 8192];             // in_proj output (xi|z per dir)
__device__ float g_proj[2 * (size_t)M_ROWS * 96];           // x_proj output (dt_raw|B|C)
__device__ float g_dt  [2 * (size_t)M_ROWS * DI];           // dt_proj output (pre-softplus)

// bf16 hi/lo operand planes
__device__ __nv_bfloat16 g_x_hi  [(size_t)M_ROWS * DM],  g_x_lo  [(size_t)M_ROWS * DM];
__device__ __nv_bfloat16 g_inw_hi[(size_t)8192 * DM],    g_inw_lo[(size_t)8192 * DM];
__device__ __nv_bfloat16 g_xw_hi [2 * 96 * (size_t)DI],  g_xw_lo [2 * 96 * (size_t)DI];
__device__ __nv_bfloat16 g_dtw_hi[2 * (size_t)DI * DR],  g_dtw_lo[2 * (size_t)DI * DR];
__device__ __nv_bfloat16 g_ow_hi [2 * (size_t)DM * DI],  g_ow_lo [2 * (size_t)DM * DI];
__device__ __nv_bfloat16 g_xc_hi [2 * (size_t)M_ROWS * DI], g_xc_lo[2 * (size_t)M_ROWS * DI];
__device__ __nv_bfloat16 g_dtr_hi[2 * (size_t)M_ROWS * DR], g_dtr_lo[2 * (size_t)M_ROWS * DR];
__device__ __nv_bfloat16 g_y_hi  [2 * (size_t)M_ROWS * DI], g_y_lo [2 * (size_t)M_ROWS * DI];

__device__ __forceinline__ void split2(float v, __nv_bfloat16& h, __nv_bfloat16& l) {
    h = __float2bfloat16_rn(v);
    l = __float2bfloat16_rn(v - __bfloat162float(h));
}

// ============================================================================
// PTX helpers (sm_80-class only: valid on base sm_103 target)
// ============================================================================
__device__ __forceinline__ uint32_t smem_u32(const void* p) {
    uint32_t a;
    asm("{ .reg .u64 t; cvta.to.shared.u64 t, %1; cvt.u32.u64 %0, t; }" : "=r"(a) : "l"(p));
    return a;
}
__device__ __forceinline__ void cpa16(uint32_t dst, const void* src) {
    asm volatile("cp.async.cg.shared.global [%0], [%1], 16;" :: "r"(dst), "l"(src) : "memory");
}
__device__ __forceinline__ void cpa16p(uint32_t dst, const void* src, int sz) {
    asm volatile("cp.async.cg.shared.global [%0], [%1], 16, %2;" :: "r"(dst), "l"(src), "r"(sz) : "memory");
}
__device__ __forceinline__ void cp_commit() {
    asm volatile("cp.async.commit_group;" ::: "memory");
}
template <int N>
__device__ __forceinline__ void cp_wait() {
    asm volatile("cp.async.wait_group %0;" :: "n"(N) : "memory");
}
__device__ __forceinline__ void ldsm_x4(uint32_t* r, uint32_t addr) {
    asm volatile("ldmatrix.sync.aligned.m8n8.x4.shared.b16 {%0,%1,%2,%3}, [%4];"
                 : "=r"(r[0]), "=r"(r[1]), "=r"(r[2]), "=r"(r[3]) : "r"(addr));
}
__device__ __forceinline__ void ldsm_x2(uint32_t* r, uint32_t addr) {
    asm volatile("ldmatrix.sync.aligned.m8n8.x2.shared.b16 {%0,%1}, [%2];"
                 : "=r"(r[0]), "=r"(r[1]) : "r"(addr));
}
__device__ __forceinline__ void mma_bf16(float* d, const uint32_t* a, const uint32_t* b) {
    asm volatile("mma.sync.aligned.m16n8k16.row.col.f32.bf16.bf16.f32 "
                 "{%0,%1,%2,%3}, {%4,%5,%6,%7}, {%8,%9}, {%0,%1,%2,%3};"
                 : "+f"(d[0]), "+f"(d[1]), "+f"(d[2]), "+f"(d[3])
                 : "r"(a[0]), "r"(a[1]), "r"(a[2]), "r"(a[3]), "r"(b[0]), "r"(b[1]));
}

// ============================================================================
// Shared GEMM machinery: 128x128 tile, K-chunk 32, 256 threads (2x4 warps,
// 64x32 warp tiles), cp.async double-buffered smem, rows padded to 40 halves.
// bf16x3 split: acc += Ah*Bh + Ah*Bl + Al*Bh  (fp32 accumulate)
// ============================================================================
#define ROW_H 40
#define PLANE (128 * ROW_H * 2)          // 10240 B
#define OFF_AH 0
#define OFF_AL (PLANE)
#define OFF_BH (2 * PLANE)
#define OFF_BL (3 * PLANE)
#define STAGE  (4 * PLANE)               // 40960 B
#define GEMM_SMEM (2 * STAGE)            // 81920 B

struct GemmCtx {
    uint32_t sb;
    int tid, lane, warp, wm, wn, bm, bn;
    uint32_t a_lane_off, b_lane_off;
};

__device__ __forceinline__ void gemm_init(GemmCtx& g, char* smem) {
    g.sb = smem_u32(smem);
    g.tid = threadIdx.x;
    g.lane = g.tid & 31;
    g.warp = g.tid >> 5;
    g.wm = g.warp >> 2;
    g.wn = g.warp & 3;
    g.bm = blockIdx.y * 128;
    g.bn = blockIdx.x * 128;
    g.a_lane_off = (uint32_t)((g.lane & 15) * ROW_H + 8 * (g.lane >> 4)) * 2;
    g.b_lane_off = (uint32_t)((g.lane & 7) * ROW_H + 8 * ((g.lane >> 3) & 1)) * 2;
}

__device__ __forceinline__ void gemm_load_chunk(
    const GemmCtx& g, int s, int k0, int K,
    const __nv_bfloat16* __restrict__ Ahi, const __nv_bfloat16* __restrict__ Alo,
    const __nv_bfloat16* __restrict__ Bhi, const __nv_bfloat16* __restrict__ Blo,
    int Nact)
{
    const uint32_t st = g.sb + s * STAGE;
#pragma unroll
    for (int it = 0; it < 2; ++it) {
        const int i   = g.tid + it * 256;
        const int row = i >> 2;
        const int c8  = (i & 3) * 8;
        const uint32_t so = (uint32_t)(row * ROW_H + c8) * 2;
        const size_t ga = (size_t)(g.bm + row) * K + k0 + c8;
        cpa16(st + OFF_AH + so, Ahi + ga);
        cpa16(st + OFF_AL + so, Alo + ga);
        const size_t gb = (size_t)(g.bn + row) * K + k0 + c8;
        const int sz = (g.bn + row < Nact) ? 16 : 0;
        cpa16p(st + OFF_BH + so, Bhi + gb, sz);
        cpa16p(st + OFF_BL + so, Blo + gb, sz);
    }
}

// Pass-major MMA schedule: same-accumulator reuse distance = 4 independent
// MMAs (was 1 -> dependent-chain stalls pinned tensor util at ~45%).
__device__ __forceinline__ void gemm_compute_chunk(const GemmCtx& g, int s, float acc[4][4][4]) {
    const uint32_t st = g.sb + s * STAGE;
#pragma unroll
    for (int k16 = 0; k16 < 32; k16 += 16) {
        const uint32_t ak = g.a_lane_off + k16 * 2;
        const uint32_t bk = g.b_lane_off + k16 * 2;
        uint32_t bh[4][2], bl[4][2];
#pragma unroll
        for (int j = 0; j < 4; ++j) {
            const uint32_t bo = (uint32_t)((g.wn * 32 + j * 8) * ROW_H) * 2 + bk;
            ldsm_x2(bh[j], st + OFF_BH + bo);
            ldsm_x2(bl[j], st + OFF_BL + bo);
        }
#pragma unroll
        for (int i = 0; i < 4; ++i) {
            const uint32_t ao = (uint32_t)((g.wm * 64 + i * 16) * ROW_H) * 2 + ak;
            uint32_t ah[4], al[4];
            ldsm_x4(ah, st + OFF_AH + ao);
            ldsm_x4(al, st + OFF_AL + ao);
            // pass 1: Ah * Bh  (j-major: 4 independent MMAs)
#pragma unroll
            for (int j = 0; j < 4; ++j) mma_bf16(acc[i][j], ah, bh[j]);
            // pass 2: Ah * Bl
#pragma unroll
            for (int j = 0; j < 4; ++j) mma_bf16(acc[i][j], ah, bl[j]);
            // pass 3: Al * Bh
#pragma unroll
            for (int j = 0; j < 4; ++j) mma_bf16(acc[i][j], al, bh[j]);
        }
    }
}

// ============================================================================
// k_gemm_z: C[z][M,N] = A[z][M,K] @ B[z][N,K]^T   (z = blockIdx.z, strides)
// Optional dtr epilogue: cols<64 also split to g_dtr_hi/lo (x_proj only).
// ============================================================================
__global__ void __launch_bounds__(256, 2) k_gemm_z(
    const __nv_bfloat16* __restrict__ Ahi, const __nv_bfloat16* __restrict__ Alo, size_t aStride,
    const __nv_bfloat16* __restrict__ Bhi, const __nv_bfloat16* __restrict__ Blo, size_t bStride,
    float* __restrict__ C, size_t cStride, int K, int Nact, int ldc, int doDtr)
{
    extern __shared__ char smem[];
    GemmCtx g;
    gemm_init(g, smem);
    const int z = blockIdx.z;
    Ahi += (size_t)z * aStride; Alo += (size_t)z * aStride;
    Bhi += (size_t)z * bStride; Blo += (size_t)z * bStride;
    C   += (size_t)z * cStride;
    const int nch = K >> 5;

    float acc[4][4][4];
#pragma unroll
    for (int i = 0; i < 4; i++)
#pragma unroll
        for (int j = 0; j < 4; j++)
#pragma unroll
            for (int k = 0; k < 4; k++) acc[i][j][k] = 0.f;

    gemm_load_chunk(g, 0, 0, K, Ahi, Alo, Bhi, Blo, Nact);
    cp_commit();

    for (int c = 0; c < nch; ++c) {
        if (c + 1 < nch) {
            gemm_load_chunk(g, (c + 1) & 1, (c + 1) << 5, K, Ahi, Alo, Bhi, Blo, Nact);
            cp_commit();
            cp_wait<1>();
        } else {
            cp_wait<0>();
        }
        __syncthreads();
        gemm_compute_chunk(g, c & 1, acc);
        __syncthreads();
    }

    const int gid = g.lane >> 2;
    const int tig = g.lane & 3;
#pragma unroll
    for (int i = 0; i < 4; ++i) {
        const int row = g.bm + g.wm * 64 + i * 16 + gid;
#pragma unroll
        for (int j = 0; j < 4; ++j) {
            const int col = g.bn + g.wn * 32 + j * 8 + tig * 2;
            if (col < Nact) {
                *(float2*)&C[(size_t)row * ldc + col]       = make_float2(acc[i][j][0], acc[i][j][1]);
                *(float2*)&C[(size_t)(row + 8) * ldc + col] = make_float2(acc[i][j][2], acc[i][j][3]);
                if (doDtr && col < DR) {
                    __nv_bfloat16 h0, l0, h1, l1;
                    size_t d0 = ((size_t)z * M_ROWS + row) * DR + col;
                    split2(acc[i][j][0], h0, l0); split2(acc[i][j][1], h1, l1);
                    g_dtr_hi[d0] = h0; g_dtr_hi[d0 + 1] = h1;
                    g_dtr_lo[d0] = l0; g_dtr_lo[d0 + 1] = l1;
                    size_t d8 = d0 + 8 * DR;
                    split2(acc[i][j][2], h0, l0); split2(acc[i][j][3], h1, l1);
                    g_dtr_hi[d8] = h0; g_dtr_hi[d8 + 1] = h1;
                    g_dtr_lo[d8] = l0; g_dtr_lo[d8 + 1] = l1;
                }
            }
        }
    }
}

// ============================================================================
// k_gemm_cat: out = y0 @ ow0^T + y1 @ ow1^T  (K-concatenated, single pass)
// ============================================================================
__global__ void __launch_bounds__(256, 2) k_gemm_cat(
    const __nv_bfloat16* __restrict__ A0hi, const __nv_bfloat16* __restrict__ A0lo,
    const __nv_bfloat16* __restrict__ A1hi, const __nv_bfloat16* __restrict__ A1lo,
    const __nv_bfloat16* __restrict__ B0hi, const __nv_bfloat16* __restrict__ B0lo,
    const __nv_bfloat16* __restrict__ B1hi, const __nv_bfloat16* __restrict__ B1lo,
    float* __restrict__ C, int Kh, int Nact, int ldc)
{
    extern __shared__ char smem[];
    GemmCtx g;
    gemm_init(g, smem);
    const int nch_h = Kh >> 5;       // chunks per half
    const int nch = nch_h * 2;

    float acc[4][4][4];
#pragma unroll
    for (int i = 0; i < 4; i++)
#pragma unroll
        for (int j = 0; j < 4; j++)
#pragma unroll
            for (int k = 0; k < 4; k++) acc[i][j][k] = 0.f;

    auto load = [&](int c, int s) {
        if (c < nch_h)
            gemm_load_chunk(g, s, c << 5, Kh, A0hi, A0lo, B0hi, B0lo, Nact);
        else
            gemm_load_chunk(g, s, (c - nch_h) << 5, Kh, A1hi, A1lo, B1hi, B1lo, Nact);
    };

    load(0, 0);
    cp_commit();
    for (int c = 0; c < nch; ++c) {
        if (c + 1 < nch) {
            load(c + 1, (c + 1) & 1);
            cp_commit();
            cp_wait<1>();
        } else {
            cp_wait<0>();
        }
        __syncthreads();
        gemm_compute_chunk(g, c & 1, acc);
        __syncthreads();
    }

    const int gid = g.lane >> 2;
    const int tig = g.lane & 3;
#pragma unroll
    for (int i = 0; i < 4; ++i) {
        const int row = g.bm + g.wm * 64 + i * 16 + gid;
#pragma unroll
        for (int j = 0; j < 4; ++j) {
            const int col = g.bn + g.wn * 32 + j * 8 + tig * 2;
            if (col < Nact) {
                *(float2*)&C[(size_t)row * ldc + col]       = make_float2(acc[i][j][0], acc[i][j][1]);
                *(float2*)&C[(size_t)(row + 8) * ldc + col] = make_float2(acc[i][j][2], acc[i][j][3]);
            }
        }
    }
}

// ============================================================================
// Fused fp32 -> bf16 hi/lo conversion for all 5 input tensors (one launch)
// ============================================================================
#define N4_X   2097152u   // 8192*1024/4
#define N4_INW 2097152u   // 8192*1024/4
#define N4_XW  98304u     // 2*96*2048/4
#define N4_DTW 65536u     // 2*2048*64/4
#define N4_OW  1048576u   // 2*1024*2048/4
#define N4_TOT (N4_X + N4_INW + N4_XW + N4_DTW + N4_OW)

__global__ void k_cvt_all(const float4* __restrict__ x, const float4* __restrict__ inw,
                          const float4* __restrict__ xw, const float4* __restrict__ dtw,
                          const float4* __restrict__ ow) {
    uint32_t i = blockIdx.x * blockDim.x + threadIdx.x;
    if (i >= N4_TOT) return;
    const float4* src;
    __nv_bfloat16 *hi, *lo;
    uint32_t off = i;
    if (i < N4_X)                         { src = x;   hi = g_x_hi;   lo = g_x_lo; }
    else if ((off -= N4_X)   < N4_INW)    { src = inw; hi = g_inw_hi; lo = g_inw_lo; }
    else if ((off -= N4_INW) < N4_XW)     { src = xw;  hi = g_xw_hi;  lo = g_xw_lo; }
    else if ((off -= N4_XW)  < N4_DTW)    { src = dtw; hi = g_dtw_hi; lo = g_dtw_lo; }
    else { off -= N4_DTW;                   src = ow;  hi = g_ow_hi;  lo = g_ow_lo; }

    float4 v = src[off];
    __nv_bfloat16 h0, h1, h2, h3, l0, l1, l2, l3;
    split2(v.x, h0, l0); split2(v.y, h1, l1); split2(v.z, h2, l2); split2(v.w, h3, l3);
    __nv_bfloat162* H = (__nv_bfloat162*)hi;
    __nv_bfloat162* L = (__nv_bfloat162*)lo;
    H[2 * (size_t)off]     = __nv_bfloat162(h0, h1);
    H[2 * (size_t)off + 1] = __nv_bfloat162(h2, h3);
    L[2 * (size_t)off]     = __nv_bfloat162(l0, l1);
    L[2 * (size_t)off + 1] = __nv_bfloat162(l2, l3);
}

// ============================================================================
// Depthwise conv (causal fwd / anti-causal bwd) + SiLU -> xc hi/lo planes
// ============================================================================
__global__ void k_conv(const float* __restrict__ cw, const float* __restrict__ cb) {
    size_t idx = (size_t)blockIdx.x * blockDim.x + threadIdx.x;
    if (idx >= (size_t)2 * M_ROWS * DI) return;
    int e = (int)(idx % DI);
    size_t r = idx / DI;
    int m = (int)(r % M_ROWS);
    int dir = (int)(r / M_ROWS);
    int l = m % L_SEQ;
    int b = m / L_SEQ;

    float acc = cb[dir * DI + e];
    const float* w4 = cw + ((size_t)dir * DI + e) * 4;
#pragma unroll
    for (int k = 0; k < 4; k++) {
        int tl = (dir == 0) ? (l - 3 + k) : (l + 3 - k);
        if (tl >= 0 && tl < L_SEQ)
            acc = fmaf(w4[k], g_xz[((size_t)(b * L_SEQ + tl)) * 8192 + dir * 4096 + e], acc);
    }
    float xc = acc / (1.f + __expf(-acc));   // silu
    __nv_bfloat16 h, lo;
    split2(xc, h, lo);
    size_t o = ((size_t)dir * M_ROWS + m) * DI + e;
    g_xc_hi[o] = h;
    g_xc_lo[o] = lo;
}

// ============================================================================
// Selective scan: 128-thread blocks (4 warps -> 4 SMSPs), 4-deep register-ring
// prefetch on all 5 input streams. Fuses softplus, recurrence, D-skip, gating.
// ============================================================================
__global__ void __launch_bounds__(128) k_scan(const float* __restrict__ dt_b,
                                              const float* __restrict__ A_log,
                                              const float* __restrict__ Dp) {
    const int tid  = threadIdx.x;
    const int lane = tid & 31;
    const int warp = tid >> 5;
    const int dir  = blockIdx.z;
    const int b    = blockIdx.y;
    const int e    = blockIdx.x * 128 + tid;

    __shared__ float sB[4][16], sC[4][16];

    float a[16];
#pragma unroll
    for (int s = 0; s < 16; s++)
        a[s] = -__expf(A_log[((size_t)dir * DI + e) * 16 + s]);

    const float bias  = dt_b[dir * DI + e];
    const float dcoef = Dp[dir * DI + e];

    float h[16];
#pragma unroll
    for (int s = 0; s < 16; s++) h[s] = 0.f;

    const size_t base_de   = (size_t)dir * M_ROWS * DI;
    const size_t proj_base = (size_t)dir * M_ROWS * 96;
    const size_t brow      = (size_t)b * L_SEQ;

    // 4-deep prefetch ring
    float rbc[4], rdt[4], rxh[4], rxl[4], rz[4];
#pragma unroll
    for (int p = 0; p < 4; p++) {
        const int tt = dir ? (L_SEQ - 1 - p) : p;
        const size_t m = brow + tt;
        rbc[p] = g_proj[proj_base + m * 96 + 64 + lane];
        rdt[p] = g_dt[base_de + m * DI + e];
        rxh[p] = __bfloat162float(g_xc_hi[base_de + m * DI + e]);
        rxl[p] = __bfloat162float(g_xc_lo[base_de + m * DI + e]);
        rz[p]  = g_xz[m * 8192 + dir * 4096 + 2048 + e];
    }

    for (int t0 = 0; t0 < L_SEQ; t0 += 4) {
#pragma unroll
        for (int u = 0; u < 4; u++) {
            const int t  = t0 + u;
            const int tt = dir ? (L_SEQ - 1 - t) : t;
            const size_t m = brow + tt;

            const float bc = rbc[u], dtv = rdt[u], xh = rxh[u], xl = rxl[u], zz = rz[u];

            // prefetch t+4 into the just-freed slot (overlaps with compute)
            const int tp = t + 4;
            if (tp < L_SEQ) {
                const int tq = dir ? (L_SEQ - 1 - tp) : tp;
                const size_t mp = brow + tq;
                rbc[u] = g_proj[proj_base + mp * 96 + 64 + lane];
                rdt[u] = g_dt[base_de + mp * DI + e];
                rxh[u] = __bfloat162float(g_xc_hi[base_de + mp * DI + e]);
                rxl[u] = __bfloat162float(g_xc_lo[base_de + mp * DI + e]);
                rz[u]  = g_xz[mp * 8192 + dir * 4096 + 2048 + e];
            }

            if (lane < 16) sB[warp][lane] = bc; else sC[warp][lane - 16] = bc;
            __syncwarp();

            const float v   = dtv + bias;
            const float dt  = (v > 15.f) ? v : log1pf(__expf(v));
            const float x   = xh + xl;
            const float dtx = dt * x;

            float y = 0.f;
#pragma unroll
            for (int s = 0; s < 16; s++) {
                float dA = __expf(dt * a[s]);
                h[s] = fmaf(h[s], dA, dtx * sB[warp][s]);
                y    = fmaf(h[s], sC[warp][s], y);
            }
            const float yv  = fmaf(x, dcoef, y);
            const float sz  = zz / (1.f + __expf(-zz));
            const float out = yv * sz;
            __nv_bfloat16 hh, ll;
            split2(out, hh, ll);
            const size_t o = base_de + m * DI + e;
            g_y_hi[o] = hh;
            g_y_lo[o] = ll;
            __syncwarp();
        }
    }
}

// ============================================================================
extern "C" void kernel_launch(void* const* d_in, const int* in_sizes, int n_in,
                              void* d_out, int out_size) {
    const float* x      = (const float*)d_in[0];
    const float* in_w   = (const float*)d_in[1];
    const float* conv_w = (const float*)d_in[2];
    const float* conv_b = (const float*)d_in[3];
    const float* x_w    = (const float*)d_in[4];
    const float* dt_w   = (const float*)d_in[5];
    const float* dt_bv  = (const float*)d_in[6];
    const float* A_log  = (const float*)d_in[7];
    const float* Dp     = (const float*)d_in[8];
    const float* out_w  = (const float*)d_in[9];
    float* out = (float*)d_out;

    cudaFuncSetAttribute(k_gemm_z,   cudaFuncAttributeMaxDynamicSharedMemorySize, GEMM_SMEM);
    cudaFuncSetAttribute(k_gemm_cat, cudaFuncAttributeMaxDynamicSharedMemorySize, GEMM_SMEM);

    float *xz, *proj, *dtv;
    __nv_bfloat16 *xhi, *xlo, *inwhi, *inwlo, *xwhi, *xwlo, *dtwhi, *dtwlo, *owhi, *owlo;
    __nv_bfloat16 *xchi, *xclo, *dtrhi, *dtrlo, *yhi, *ylo;
    cudaGetSymbolAddress((void**)&xz, g_xz);
    cudaGetSymbolAddress((void**)&proj, g_proj);
    cudaGetSymbolAddress((void**)&dtv, g_dt);
    cudaGetSymbolAddress((void**)&xhi, g_x_hi);     cudaGetSymbolAddress((void**)&xlo, g_x_lo);
    cudaGetSymbolAddress((void**)&inwhi, g_inw_hi); cudaGetSymbolAddress((void**)&inwlo, g_inw_lo);
    cudaGetSymbolAddress((void**)&xwhi, g_xw_hi);   cudaGetSymbolAddress((void**)&xwlo, g_xw_lo);
    cudaGetSymbolAddress((void**)&dtwhi, g_dtw_hi); cudaGetSymbolAddress((void**)&dtwlo, g_dtw_lo);
    cudaGetSymbolAddress((void**)&owhi, g_ow_hi);   cudaGetSymbolAddress((void**)&owlo, g_ow_lo);
    cudaGetSymbolAddress((void**)&xchi, g_xc_hi);   cudaGetSymbolAddress((void**)&xclo, g_xc_lo);
    cudaGetSymbolAddress((void**)&dtrhi, g_dtr_hi); cudaGetSymbolAddress((void**)&dtrlo, g_dtr_lo);
    cudaGetSymbolAddress((void**)&yhi, g_y_hi);     cudaGetSymbolAddress((void**)&ylo, g_y_lo);

    // 0) all fp32 -> bf16 hi/lo conversions, one launch
    k_cvt_all<<<(N4_TOT + 255) / 256, 256>>>((const float4*)x, (const float4*)in_w,
                                             (const float4*)x_w, (const float4*)dt_w,
                                             (const float4*)out_w);

    // 1) in_proj: xz = x @ in_w^T  (M=8192, N=8192, K=1024)
    k_gemm_z<<<dim3(64, 64, 1), 256, GEMM_SMEM>>>(xhi, xlo, 0, inwhi, inwlo, 0,
                                                  xz, 0, DM, 8192, 8192, 0);

    // 2) depthwise conv + silu -> xc hi/lo
    k_conv<<<(unsigned)(((size_t)2 * M_ROWS * DI) / 256), 256>>>(conv_w, conv_b);

    // 3) x_proj (both dirs): proj = xc @ x_proj_w^T (N=96, K=2048); dtr fused
    k_gemm_z<<<dim3(1, 64, 2), 256, GEMM_SMEM>>>(
        xchi, xclo, (size_t)M_ROWS * DI, xwhi, xwlo, (size_t)96 * DI,
        proj, (size_t)M_ROWS * 96, DI, 96, 96, 1);

    // 4) dt_proj (both dirs): dt = dt_raw @ dt_proj_w^T (N=2048, K=64)
    k_gemm_z<<<dim3(16, 64, 2), 256, GEMM_SMEM>>>(
        dtrhi, dtrlo, (size_t)M_ROWS * DR, dtwhi, dtwlo, (size_t)DI * DR,
        dtv, (size_t)M_ROWS * DI, DR, DI, DI, 0);

    // 5) selective scan + gating -> y hi/lo
    k_scan<<<dim3(DI / 128, BSZ, 2), 128>>>(dt_bv, A_log, Dp);

    // 6) out_proj (both dirs, K-concatenated single pass)
    k_gemm_cat<<<dim3(8, 64, 1), 256, GEMM_SMEM>>>(
        yhi, ylo, yhi + (size_t)M_ROWS * DI, ylo + (size_t)M_ROWS * DI,
        owhi, owlo, owhi + (size_t)DM * DI, owlo + (size_t)DM * DI,
        out, DI, DM, DM);
}